// round 4
// baseline (speedup 1.0000x reference)
#include <cuda_runtime.h>
#include <math.h>

#define S_ 64
#define B_ 32
#define H_ 1024
#define E_ 512
#define V_ 32000
#define HB (H_*B_)          // 32768
#define KSPLIT 8

// ---------------- device scratch (no allocs allowed) ----------------
__device__ float g_xT[S_*E_*B_];        // [t][e][b]   4 MB
__device__ float g_h0T[(S_+1)*HB];      // [t][i][b]   8.5 MB
__device__ float g_h1T[(S_+1)*HB];      // [t][i][b]
__device__ float g_tops[S_*B_*H_];      // [t][b][i]   (std layout for out GEMM)
__device__ float g_part[KSPLIT*HB];     // k-split partials

// ---------------- init: transpose initial hidden --------------------
__global__ void init_hidden_k(const float* __restrict__ hidden) {
    int idx = blockIdx.x * blockDim.x + threadIdx.x;   // < 2*32*1024
    if (idx >= 2*B_*H_) return;
    int l = idx >> 15;            // /32768
    int rem = idx & 32767;
    int b = rem >> 10;            // /1024
    int i = rem & 1023;
    float v = hidden[idx];
    float* dst = l ? g_h1T : g_h0T;
    dst[i*B_ + b] = v;            // slot 0
}

// ---------------- embedding gather: xT[t][e][b] ----------------------
__global__ void embed_all_k(const int* __restrict__ tok, const float* __restrict__ emb) {
    int idx = blockIdx.x * blockDim.x + threadIdx.x;   // < 64*512*32
    if (idx >= S_*E_*B_) return;
    int b = idx & 31;
    int e = (idx >> 5) & 511;
    int t = idx >> 14;
    int tk = tok[t*B_ + b];
    g_xT[idx] = emb[(size_t)tk * E_ + e];
}

// ---------------- per-layer K-split GEMM -----------------------------
// out partial[seg][i][b] += sum over k-segment of W[i][k]*act[k][b]
// combined K = KA (x part, from aT [KA][B]) then H_ (from hT [H][B]).
// block: 128 threads, tile 64 i x 32 b, microtile 4i x 4b.
#define KC 32
__global__ void rnn_layer_gemm(const float* __restrict__ Wx, const float* __restrict__ Wh,
                               const float* __restrict__ aT, const float* __restrict__ hT,
                               float* __restrict__ part, int KA, int seglen) {
    __shared__ float Ws[64][33];
    __shared__ float As[KC][32];
    int tid = threadIdx.x;
    int bq = tid & 7;        // b quad index (0..7)
    int iq = tid >> 3;       // i quad index (0..15)
    int i0 = blockIdx.x * 64;
    int k0 = blockIdx.y * seglen;

    float acc[4][4];
#pragma unroll
    for (int j = 0; j < 4; j++)
#pragma unroll
        for (int bb = 0; bb < 4; bb++) acc[j][bb] = 0.f;

    for (int kb = k0; kb < k0 + seglen; kb += KC) {
        bool isx = (kb < KA);
        const float* Wp = isx ? (Wx + (size_t)i0 * KA + kb)
                              : (Wh + (size_t)i0 * H_ + (kb - KA));
        int ldw = isx ? KA : H_;
        const float* ap = isx ? (aT + (size_t)kb * B_)
                              : (hT + (size_t)(kb - KA) * B_);
        // stage W tile: 64 rows x 32
#pragma unroll
        for (int q = 0; q < 4; q++) {
            int f = tid + 128 * q;           // 0..511 float4 slots
            int r = f >> 3;
            int c4 = (f & 7) << 2;
            float4 w4 = *(const float4*)(Wp + (size_t)r * ldw + c4);
            Ws[r][c4 + 0] = w4.x; Ws[r][c4 + 1] = w4.y;
            Ws[r][c4 + 2] = w4.z; Ws[r][c4 + 3] = w4.w;
        }
        // stage activations: 32k x 32b contiguous = 4KB
#pragma unroll
        for (int q = 0; q < 2; q++) {
            int f = tid + 128 * q;           // 0..255
            ((float4*)As)[f] = ((const float4*)ap)[f];
        }
        __syncthreads();
#pragma unroll
        for (int k = 0; k < KC; k++) {
            float4 a4 = *(const float4*)&As[k][bq << 2];
#pragma unroll
            for (int j = 0; j < 4; j++) {
                float w = Ws[iq * 4 + j][k];
                acc[j][0] += w * a4.x;
                acc[j][1] += w * a4.y;
                acc[j][2] += w * a4.z;
                acc[j][3] += w * a4.w;
            }
        }
        __syncthreads();
    }
    float* pp = part + (size_t)blockIdx.y * HB;
#pragma unroll
    for (int j = 0; j < 4; j++) {
        int i = i0 + iq * 4 + j;
        float4 v = make_float4(acc[j][0], acc[j][1], acc[j][2], acc[j][3]);
        *(float4*)(pp + (size_t)i * B_ + (bq << 2)) = v;
    }
}

// ---------------- reduce + bias + tanh epilogue ----------------------
__global__ void rnn_epi(const float* __restrict__ part, const float* __restrict__ bias,
                        float* __restrict__ outT, float* __restrict__ outStd) {
    int idx = blockIdx.x * blockDim.x + threadIdx.x;  // < HB
    if (idx >= HB) return;
    int i = idx >> 5;
    int b = idx & 31;
    float s = bias[i];
#pragma unroll
    for (int ks = 0; ks < KSPLIT; ks++) s += part[ks * HB + idx];
    float v = tanhf(s);
    outT[idx] = v;
    if (outStd) outStd[(size_t)b * H_ + i] = v;
}

// ---------------- output projection SGEMM ----------------------------
// C[m][n] = A[m][:1024] . Bw[n][:1024] + bout[n]
// A = tops [2048 x 1024] row-major, Bw = Wout [32000 x 1024] row-major
#define BM 64
#define BN 128
#define BK 16
__global__ void out_gemm(const float* __restrict__ A, const float* __restrict__ Bw,
                         const float* __restrict__ bout, float* __restrict__ C) {
    __shared__ float As[BK][BM + 4];   // 68 floats/row -> 16B aligned rows
    __shared__ float Bs[BK][BN + 4];   // 132 floats/row -> 16B aligned rows
    int tid = threadIdx.x;
    int tx = tid & 15;        // n tile group (16 x 8n)
    int ty = tid >> 4;        // m tile group (16 x 4m)
    int m0 = blockIdx.y * BM;
    int n0 = blockIdx.x * BN;

    float acc[4][8];
#pragma unroll
    for (int a = 0; a < 4; a++)
#pragma unroll
        for (int b = 0; b < 8; b++) acc[a][b] = 0.f;

    int la_m = tid >> 2;            // 0..63
    int la_k = (tid & 3) << 2;      // 0,4,8,12

    for (int kb = 0; kb < H_; kb += BK) {
        float4 a4 = *(const float4*)(A + (size_t)(m0 + la_m) * H_ + kb + la_k);
        As[la_k + 0][la_m] = a4.x; As[la_k + 1][la_m] = a4.y;
        As[la_k + 2][la_m] = a4.z; As[la_k + 3][la_m] = a4.w;
        float4 b4 = *(const float4*)(Bw + (size_t)(n0 + la_m) * H_ + kb + la_k);
        Bs[la_k + 0][la_m] = b4.x; Bs[la_k + 1][la_m] = b4.y;
        Bs[la_k + 2][la_m] = b4.z; Bs[la_k + 3][la_m] = b4.w;
        float4 b5 = *(const float4*)(Bw + (size_t)(n0 + la_m + 64) * H_ + kb + la_k);
        Bs[la_k + 0][la_m + 64] = b5.x; Bs[la_k + 1][la_m + 64] = b5.y;
        Bs[la_k + 2][la_m + 64] = b5.z; Bs[la_k + 3][la_m + 64] = b5.w;
        __syncthreads();
#pragma unroll
        for (int kk = 0; kk < BK; kk++) {
            float4 av  = *(const float4*)&As[kk][ty << 2];
            float4 bv0 = *(const float4*)&Bs[kk][tx << 2];
            float4 bv1 = *(const float4*)&Bs[kk][(tx << 2) + 64];
            float am[4] = {av.x, av.y, av.z, av.w};
            float bn[8] = {bv0.x, bv0.y, bv0.z, bv0.w, bv1.x, bv1.y, bv1.z, bv1.w};
#pragma unroll
            for (int a = 0; a < 4; a++)
#pragma unroll
                for (int b = 0; b < 8; b++) acc[a][b] += am[a] * bn[b];
        }
        __syncthreads();
    }

    int n = n0 + (tx << 2);
    float bo0 = bout[n + 0], bo1 = bout[n + 1], bo2 = bout[n + 2], bo3 = bout[n + 3];
    float bo4 = bout[n + 64], bo5 = bout[n + 65], bo6 = bout[n + 66], bo7 = bout[n + 67];
#pragma unroll
    for (int mm = 0; mm < 4; mm++) {
        size_t row = (size_t)(m0 + (ty << 2) + mm) * V_;
        float4 r0 = make_float4(acc[mm][0] + bo0, acc[mm][1] + bo1,
                                acc[mm][2] + bo2, acc[mm][3] + bo3);
        float4 r1 = make_float4(acc[mm][4] + bo4, acc[mm][5] + bo5,
                                acc[mm][6] + bo6, acc[mm][7] + bo7);
        *(float4*)(C + row + n)      = r0;
        *(float4*)(C + row + n + 64) = r1;
    }
}

// ---------------- hidden_final writeback ------------------------------
__global__ void finalize_k(float* __restrict__ outTail) {
    int idx = blockIdx.x * blockDim.x + threadIdx.x;   // < 2*32*1024
    if (idx >= 2*B_*H_) return;
    int l = idx >> 15;
    int rem = idx & 32767;
    int b = rem >> 10;
    int i = rem & 1023;
    const float* src = (l ? g_h1T : g_h0T) + (size_t)S_ * HB;
    outTail[idx] = src[i*B_ + b];
}

// ---------------- launch ---------------------------------------------
extern "C" void kernel_launch(void* const* d_in, const int* in_sizes, int n_in,
                              void* d_out, int out_size) {
    const int*   tok   = (const int*)  d_in[0];
    const float* hidden= (const float*)d_in[1];
    const float* emb   = (const float*)d_in[2];
    const float* Wx0   = (const float*)d_in[3];
    const float* Wh0   = (const float*)d_in[4];
    const float* bh0   = (const float*)d_in[5];
    const float* Wx1   = (const float*)d_in[6];
    const float* Wh1   = (const float*)d_in[7];
    const float* bh1   = (const float*)d_in[8];
    const float* Wout  = (const float*)d_in[9];
    const float* bout  = (const float*)d_in[10];
    float* out = (float*)d_out;

    float *xT, *h0T, *h1T, *tops, *part;
    cudaGetSymbolAddress((void**)&xT,   g_xT);
    cudaGetSymbolAddress((void**)&h0T,  g_h0T);
    cudaGetSymbolAddress((void**)&h1T,  g_h1T);
    cudaGetSymbolAddress((void**)&tops, g_tops);
    cudaGetSymbolAddress((void**)&part, g_part);

    init_hidden_k<<<(2*B_*H_ + 255)/256, 256>>>(hidden);
    embed_all_k<<<(S_*E_*B_ + 255)/256, 256>>>(tok, emb);

    for (int t = 0; t < S_; t++) {
        // layer 0: K = E + H = 1536, seglen = 192
        rnn_layer_gemm<<<dim3(H_/64, KSPLIT), 128>>>(
            Wx0, Wh0, xT + (size_t)t*E_*B_, h0T + (size_t)t*HB, part, E_, (E_+H_)/KSPLIT);
        rnn_epi<<<(HB + 255)/256, 256>>>(part, bh0, h0T + (size_t)(t+1)*HB, (float*)0);
        // layer 1: K = H + H = 2048, seglen = 256
        rnn_layer_gemm<<<dim3(H_/64, KSPLIT), 128>>>(
            Wx1, Wh1, h0T + (size_t)(t+1)*HB, h1T + (size_t)t*HB, part, H_, (H_+H_)/KSPLIT);
        rnn_epi<<<(HB + 255)/256, 256>>>(part, bh1, h1T + (size_t)(t+1)*HB, tops + (size_t)t*B_*H_);
    }

    // logits: [2048 x 32000]
    out_gemm<<<dim3(V_/BN, (S_*B_)/BM), 256>>>(tops, Wout, bout, out);

    // hidden_final appended after logits
    finalize_k<<<(2*B_*H_ + 255)/256, 256>>>(out + (size_t)S_*B_*V_);
}